// round 3
// baseline (speedup 1.0000x reference)
#include <cuda_runtime.h>

// Problem constants (fixed by the dataset)
#define BB   16
#define NN   32
#define HH   512
#define WW   512
#define CC   512
#define SS   256    // 16*16 pooled spatial
#define EE   128
#define SPLITK 4

// Scratch (static device globals — no runtime allocation)
__device__ float g_part[SPLITK][BB * EE * SS]; // 8 MB: split-K partial sums [kc][b][e][s]
__device__ float g_mr[BB * NN * SS];           // resized masks [bn][s]
__device__ float g_minv[BB * NN];              // 1/(mask_sum + eps)

// ---------------------------------------------------------------------------
// Kernel A:
//   blocks [0,128):   split-K GEMM.  part[kc][b][e][s] = sum_{c in chunk kc} W[e][c]*F[b][c][s]
//                     Tile: 128E x 128S x 128K. 256 threads, microtile 8x8,
//                     double-buffered smem. No atomics (separate slabs).
//   blocks [128,640): bilinear mask resize (512->16) + mask sums. 256 threads,
//                     one pooled pixel per thread.
// ---------------------------------------------------------------------------
__global__ void __launch_bounds__(256) kernelA(
    const float* __restrict__ features,   // [B, C, 16, 16]
    const float* __restrict__ masks,      // [B, N, 512, 512]
    const float* __restrict__ conv_w)     // [E, C]
{
    __shared__ float sW[2][8][136];   // [buf][k][e]  (pad 136 -> 544B row, 16B aligned)
    __shared__ float sF[2][8][136];   // [buf][k][s]
    __shared__ float red[8];

    const int blk = blockIdx.x;
    const int tid = threadIdx.x;

    if (blk >= 128) {
        // ---------------- mask resize path ----------------
        const int bn = blk - 128;                 // 0..511
        const float* m = masks + (size_t)bn * (HH * WW);

        const int o = tid >> 4;                   // out row 0..15
        const int p = tid & 15;                   // out col 0..15
        // torch bilinear (align_corners=False): src = max(0,(i+0.5)*scale-0.5)
        float sy = (o + 0.5f) * ((float)HH / 16.0f) - 0.5f;
        sy = fmaxf(sy, 0.0f);
        int   y0 = (int)floorf(sy);
        float fy = sy - (float)y0;
        int   y1 = min(y0 + 1, HH - 1);
        float sx = (p + 0.5f) * ((float)WW / 16.0f) - 0.5f;
        sx = fmaxf(sx, 0.0f);
        int   x0 = (int)floorf(sx);
        float fx = sx - (float)x0;
        int   x1 = min(x0 + 1, WW - 1);

        float v00 = m[(size_t)y0 * WW + x0];
        float v01 = m[(size_t)y0 * WW + x1];
        float v10 = m[(size_t)y1 * WW + x0];
        float v11 = m[(size_t)y1 * WW + x1];
        float v = (1.0f - fy) * ((1.0f - fx) * v00 + fx * v01)
                +          fy * ((1.0f - fx) * v10 + fx * v11);

        g_mr[(size_t)bn * SS + tid] = v;

        float lsum = v;
        #pragma unroll
        for (int off = 16; off > 0; off >>= 1)
            lsum += __shfl_xor_sync(0xFFFFFFFFu, lsum, off);
        if ((tid & 31) == 0) red[tid >> 5] = lsum;
        __syncthreads();
        if (tid == 0) {
            float s = red[0] + red[1] + red[2] + red[3]
                    + red[4] + red[5] + red[6] + red[7];
            g_minv[bn] = 1.0f / (s + 1e-8f);
        }
        return;
    }

    // ---------------- GEMM path ----------------
    // blk = kc*32 + stile ; kc: K-chunk of 128 ; stile: 128-wide S tile
    const int kc    = blk >> 5;           // 0..3
    const int stile = blk & 31;           // 0..31
    const int b     = stile >> 1;         // batch
    const int s0    = (stile & 1) * 128;  // s offset within batch
    const int c0    = kc * 128;

    // microtile: 8E x 8S per thread; threads as 16 x 16
    const int te = tid >> 4;              // 0..15 -> e = te*8
    const int ts = tid & 15;              // 0..15 -> s = ts*8

    // global load roles
    const int we = tid & 127;             // W row (e)
    const int wk = (tid >> 7) << 2;       // 0 or 4 -> this thread covers k = wk..wk+3
    const int fk = tid >> 5;              // 0..7 -> F k row
    const int fs = (tid & 31) << 2;       // F s col (x4)

    const float* wp = conv_w + (size_t)we * CC + c0 + wk;
    const float* fp = features + ((size_t)b * CC + c0 + fk) * SS + s0 + fs;

    float acc[8][8];
    #pragma unroll
    for (int i = 0; i < 8; i++)
        #pragma unroll
        for (int j = 0; j < 8; j++) acc[i][j] = 0.0f;

    // prefetch tile 0
    float4 wr = *(const float4*)wp;   wp += 8;
    float4 fr = *(const float4*)fp;   fp += 8 * SS;

    // store tile 0 into buffer 0
    sW[0][wk + 0][we] = wr.x;
    sW[0][wk + 1][we] = wr.y;
    sW[0][wk + 2][we] = wr.z;
    sW[0][wk + 3][we] = wr.w;
    *(float4*)&sF[0][fk][fs] = fr;
    __syncthreads();

    #pragma unroll 1
    for (int t = 0; t < 16; t++) {
        const int cur = t & 1;
        if (t < 15) {                       // prefetch next k-tile
            wr = *(const float4*)wp;  wp += 8;
            fr = *(const float4*)fp;  fp += 8 * SS;
        }
        #pragma unroll
        for (int k = 0; k < 8; k++) {
            float4 a0 = *(const float4*)&sW[cur][k][te << 3];
            float4 a1 = *(const float4*)&sW[cur][k][(te << 3) + 4];
            float4 f0 = *(const float4*)&sF[cur][k][ts << 3];
            float4 f1 = *(const float4*)&sF[cur][k][(ts << 3) + 4];
            float av[8] = {a0.x, a0.y, a0.z, a0.w, a1.x, a1.y, a1.z, a1.w};
            float fv[8] = {f0.x, f0.y, f0.z, f0.w, f1.x, f1.y, f1.z, f1.w};
            #pragma unroll
            for (int i = 0; i < 8; i++)
                #pragma unroll
                for (int j = 0; j < 8; j++)
                    acc[i][j] += av[i] * fv[j];
        }
        if (t < 15) {                       // fill the other buffer
            const int nxt = cur ^ 1;
            sW[nxt][wk + 0][we] = wr.x;
            sW[nxt][wk + 1][we] = wr.y;
            sW[nxt][wk + 2][we] = wr.z;
            sW[nxt][wk + 3][we] = wr.w;
            *(float4*)&sF[nxt][fk][fs] = fr;
        }
        __syncthreads();
    }

    // epilogue: write raw partial sums to this chunk's slab (no atomics)
    float* slab = g_part[kc];
    #pragma unroll
    for (int i = 0; i < 8; i++) {
        const int e = (te << 3) + i;
        float* dst = slab + ((size_t)(b * EE + e)) * SS + s0 + (ts << 3);
        float4 o0 = make_float4(acc[i][0], acc[i][1], acc[i][2], acc[i][3]);
        float4 o1 = make_float4(acc[i][4], acc[i][5], acc[i][6], acc[i][7]);
        *(float4*)dst       = o0;
        *(float4*)(dst + 4) = o1;
    }
}

// ---------------------------------------------------------------------------
// Kernel B: slab-sum + BN+ReLU (on-the-fly) + mask-weighted pooling + MLP.
// Grid: 128 blocks = (b, ng); each block owns 4 (b,n) rows.
// 512 threads: tid = part*128 + e.
// ---------------------------------------------------------------------------
__global__ void __launch_bounds__(512) kernelB(
    const float* __restrict__ conv_b,
    const float* __restrict__ bn_gamma, const float* __restrict__ bn_beta,
    const float* __restrict__ bn_mean,  const float* __restrict__ bn_var,
    const float* __restrict__ w1, const float* __restrict__ b1,
    const float* __restrict__ w2, const float* __restrict__ b2,
    float* __restrict__ out)
{
    const int b  = blockIdx.x >> 3;
    const int ng = blockIdx.x & 7;
    const int n0 = ng * 4;
    const int tid  = threadIdx.x;
    const int e    = tid & 127;
    const int part = tid >> 7;           // 0..3

    __shared__ float mrs[4][SS];         // 4 resized masks
    __shared__ float px[4][4][EE];       // partial sums [part][row][e]
    __shared__ float xs[4][EE];          // obj rows
    __shared__ float hs[4][EE];          // hidden rows
    __shared__ float inv[4];

    for (int i = tid; i < 4 * SS; i += 512)
        mrs[i >> 8][i & 255] = g_mr[((size_t)(b * NN + n0 + (i >> 8))) * SS + (i & 255)];
    if (tid < 4) inv[tid] = g_minv[b * NN + n0 + tid];

    const float sc   = bn_gamma[e] * rsqrtf(bn_var[e] + 1e-5f);
    const float bias = (conv_b[e] - bn_mean[e]) * sc + bn_beta[e];
    __syncthreads();

    // pooling partials: thread (e, part) covers s in [part*64, part*64+64)
    {
        const size_t base = ((size_t)(b * EE + e)) * SS + part * 64;
        const float* pr0 = g_part[0] + base;
        const float* pr1 = g_part[1] + base;
        const float* pr2 = g_part[2] + base;
        const float* pr3 = g_part[3] + base;
        float a0 = 0.f, a1 = 0.f, a2 = 0.f, a3 = 0.f;
        #pragma unroll 4
        for (int s = 0; s < 64; s += 4) {
            float4 q0 = *(const float4*)&pr0[s];
            float4 q1 = *(const float4*)&pr1[s];
            float4 q2 = *(const float4*)&pr2[s];
            float4 q3 = *(const float4*)&pr3[s];
            float4 p;
            p.x = q0.x + q1.x + q2.x + q3.x;
            p.y = q0.y + q1.y + q2.y + q3.y;
            p.z = q0.z + q1.z + q2.z + q3.z;
            p.w = q0.w + q1.w + q2.w + q3.w;
            p.x = fmaxf(p.x * sc + bias, 0.f);
            p.y = fmaxf(p.y * sc + bias, 0.f);
            p.z = fmaxf(p.z * sc + bias, 0.f);
            p.w = fmaxf(p.w * sc + bias, 0.f);
            const int sg = part * 64 + s;
            float4 m0 = *(const float4*)&mrs[0][sg];
            float4 m1 = *(const float4*)&mrs[1][sg];
            float4 m2 = *(const float4*)&mrs[2][sg];
            float4 m3 = *(const float4*)&mrs[3][sg];
            a0 += p.x * m0.x + p.y * m0.y + p.z * m0.z + p.w * m0.w;
            a1 += p.x * m1.x + p.y * m1.y + p.z * m1.z + p.w * m1.w;
            a2 += p.x * m2.x + p.y * m2.y + p.z * m2.z + p.w * m2.w;
            a3 += p.x * m3.x + p.y * m3.y + p.z * m3.z + p.w * m3.w;
        }
        px[part][0][e] = a0;
        px[part][1][e] = a1;
        px[part][2][e] = a2;
        px[part][3][e] = a3;
    }
    __syncthreads();

    // reduce partials: thread (e, row=part)
    {
        const int rw = part;
        float v = px[0][rw][e] + px[1][rw][e] + px[2][rw][e] + px[3][rw][e];
        xs[rw][e] = v * inv[rw];
    }
    __syncthreads();

    // layer 1: thread (e, row=part)
    {
        const float* wrow = w1 + (size_t)e * EE;
        float a = 0.f;
        #pragma unroll 8
        for (int k = 0; k < EE; k += 4) {
            float4 wv = *(const float4*)&wrow[k];
            float4 xv = *(const float4*)&xs[part][k];
            a += wv.x * xv.x + wv.y * xv.y + wv.z * xv.z + wv.w * xv.w;
        }
        hs[part][e] = fmaxf(a + b1[e], 0.f);
    }
    __syncthreads();

    // layer 2
    {
        const float* wrow = w2 + (size_t)e * EE;
        float a = 0.f;
        #pragma unroll 8
        for (int k = 0; k < EE; k += 4) {
            float4 wv = *(const float4*)&wrow[k];
            float4 xv = *(const float4*)&hs[part][k];
            a += wv.x * xv.x + wv.y * xv.y + wv.z * xv.z + wv.w * xv.w;
        }
        out[((size_t)(b * NN + n0 + part)) * EE + e] = a + b2[e];
    }
}

extern "C" void kernel_launch(void* const* d_in, const int* in_sizes, int n_in,
                              void* d_out, int out_size)
{
    const float* features = (const float*)d_in[0];
    const float* masks    = (const float*)d_in[1];
    const float* conv_w   = (const float*)d_in[2];
    const float* conv_b   = (const float*)d_in[3];
    const float* bn_gamma = (const float*)d_in[4];
    const float* bn_beta  = (const float*)d_in[5];
    const float* bn_mean  = (const float*)d_in[6];
    const float* bn_var   = (const float*)d_in[7];
    const float* w1       = (const float*)d_in[8];
    const float* b1       = (const float*)d_in[9];
    const float* w2       = (const float*)d_in[10];
    const float* b2       = (const float*)d_in[11];
    float* out = (float*)d_out;

    kernelA<<<640, 256>>>(features, masks, conv_w);
    kernelB<<<128, 512>>>(conv_b, bn_gamma, bn_beta, bn_mean, bn_var,
                          w1, b1, w2, b2, out);
}

// round 4
// speedup vs baseline: 2.3472x; 2.3472x over previous
#include <cuda_runtime.h>

// Problem constants (fixed by the dataset)
#define BB   16
#define NN   32
#define HH   512
#define WW   512
#define CC   512
#define SS   256    // 16*16 pooled spatial
#define EE   128

// Scratch (static device globals — no runtime allocation)
__device__ float g_proj[BB * SS * EE];   // 2 MB: BN+ReLU'd projection, layout [b][s][e]
__device__ float g_mr[BB * NN * SS];     // resized masks [bn][s]
__device__ float g_minv[BB * NN];        // 1/(mask_sum + eps)
__device__ float g_w1T[EE * EE];         // w1 transposed: [k][e]
__device__ float g_w2T[EE * EE];         // w2 transposed: [k][e]

// ---------------------------------------------------------------------------
// Kernel A (128 threads/block, grid 642):
//   blocks [0,128):   GEMM. proj[b][s][e] = ReLU(BN(sum_c W[e][c]*F[b][c][s]))
//                     Tile 64E x 64S x full K=512. microtile 8E x 4S.
//   blocks [128,640): bilinear mask resize (512->16) + mask sums.
//   blocks 640,641:   transpose w1 -> g_w1T, w2 -> g_w2T.
// ---------------------------------------------------------------------------
__global__ void __launch_bounds__(128) kernelA(
    const float* __restrict__ features,   // [B, C, 16, 16]
    const float* __restrict__ masks,      // [B, N, 512, 512]
    const float* __restrict__ conv_w,     // [E, C]
    const float* __restrict__ conv_b,
    const float* __restrict__ bn_gamma, const float* __restrict__ bn_beta,
    const float* __restrict__ bn_mean,  const float* __restrict__ bn_var,
    const float* __restrict__ w1, const float* __restrict__ w2)
{
    __shared__ float sW[2][16][68];   // [buf][k][e]
    __shared__ float sF[2][16][68];   // [buf][k][s]
    __shared__ float red[4];
    __shared__ float ttile[32][33];

    const int blk = blockIdx.x;
    const int tid = threadIdx.x;

    if (blk >= 640) {
        // ---------------- weight transpose path ----------------
        const float* src = (blk == 640) ? w1 : w2;
        float* dstT      = (blk == 640) ? g_w1T : g_w2T;
        const int rr = tid >> 5;            // 0..3
        const int cc = tid & 31;
        for (int t = 0; t < 16; t++) {
            const int ti = t >> 2, tj = t & 3;
            #pragma unroll
            for (int rs = 0; rs < 8; rs++) {
                const int row = rs * 4 + rr;
                ttile[row][cc] = src[(size_t)(ti * 32 + row) * EE + tj * 32 + cc];
            }
            __syncthreads();
            #pragma unroll
            for (int rs = 0; rs < 8; rs++) {
                const int row = rs * 4 + rr;
                dstT[(size_t)(tj * 32 + row) * EE + ti * 32 + cc] = ttile[cc][row];
            }
            __syncthreads();
        }
        return;
    }

    if (blk >= 128) {
        // ---------------- mask resize path ----------------
        const int bn = blk - 128;                 // 0..511
        const float* m = masks + (size_t)bn * (HH * WW);
        float lsum = 0.0f;

        #pragma unroll
        for (int rep = 0; rep < 2; rep++) {
            const int t = tid + rep * 128;        // pooled pixel 0..255
            const int o = t >> 4;
            const int p = t & 15;
            float sy = (o + 0.5f) * ((float)HH / 16.0f) - 0.5f;
            sy = fmaxf(sy, 0.0f);
            int   y0 = (int)floorf(sy);
            float fy = sy - (float)y0;
            int   y1 = min(y0 + 1, HH - 1);
            float sx = (p + 0.5f) * ((float)WW / 16.0f) - 0.5f;
            sx = fmaxf(sx, 0.0f);
            int   x0 = (int)floorf(sx);
            float fx = sx - (float)x0;
            int   x1 = min(x0 + 1, WW - 1);

            float v00 = m[(size_t)y0 * WW + x0];
            float v01 = m[(size_t)y0 * WW + x1];
            float v10 = m[(size_t)y1 * WW + x0];
            float v11 = m[(size_t)y1 * WW + x1];
            float v = (1.0f - fy) * ((1.0f - fx) * v00 + fx * v01)
                    +          fy * ((1.0f - fx) * v10 + fx * v11);

            g_mr[(size_t)bn * SS + t] = v;
            lsum += v;
        }
        #pragma unroll
        for (int off = 16; off > 0; off >>= 1)
            lsum += __shfl_xor_sync(0xFFFFFFFFu, lsum, off);
        if ((tid & 31) == 0) red[tid >> 5] = lsum;
        __syncthreads();
        if (tid == 0)
            g_minv[bn] = 1.0f / (red[0] + red[1] + red[2] + red[3] + 1e-8f);
        return;
    }

    // ---------------- GEMM path ----------------
    const int et    = blk >> 6;           // 0..1  (E tile of 64)
    const int stile = blk & 63;           // 0..63
    const int b     = stile >> 2;
    const int s0    = (stile & 3) * 64;
    const int eBase = et * 64;

    const int te = tid >> 4;              // 0..7  -> e micro-row = te*8
    const int ts = tid & 15;              // 0..15 -> s micro-col = ts*4

    // W load: coalesced row segments, transposed on smem store
    const int wq  = tid & 3;              // c-quad within 16-k tile
    const int wei = tid >> 2;             // 0..31 (e rows wei and wei+32)
    const float* wp = conv_w + (size_t)(eBase + wei) * CC + (wq << 2);

    // F load: [k][s] coalesced
    const int fk  = tid >> 4;             // 0..7
    const int fsq = (tid & 15) << 2;
    const float* fp = features + ((size_t)b * CC + fk) * SS + s0 + fsq;

    float acc[8][4];
    #pragma unroll
    for (int i = 0; i < 8; i++)
        #pragma unroll
        for (int j = 0; j < 4; j++) acc[i][j] = 0.0f;

    // prefetch tile 0
    float4 wr0 = *(const float4*)wp;
    float4 wr1 = *(const float4*)(wp + 32 * CC);
    float4 fr0 = *(const float4*)fp;
    float4 fr1 = *(const float4*)(fp + 8 * SS);

    {
        const int kk = wq << 2;
        sW[0][kk + 0][wei] = wr0.x;  sW[0][kk + 0][wei + 32] = wr1.x;
        sW[0][kk + 1][wei] = wr0.y;  sW[0][kk + 1][wei + 32] = wr1.y;
        sW[0][kk + 2][wei] = wr0.z;  sW[0][kk + 2][wei + 32] = wr1.z;
        sW[0][kk + 3][wei] = wr0.w;  sW[0][kk + 3][wei + 32] = wr1.w;
        *(float4*)&sF[0][fk][fsq]     = fr0;
        *(float4*)&sF[0][fk + 8][fsq] = fr1;
    }
    __syncthreads();

    #pragma unroll 1
    for (int t = 0; t < 32; t++) {
        const int cur = t & 1;
        if (t < 31) {
            const int c0 = (t + 1) << 4;
            wr0 = *(const float4*)(wp + c0);
            wr1 = *(const float4*)(wp + 32 * CC + c0);
            fr0 = *(const float4*)(fp + (size_t)c0 * SS);
            fr1 = *(const float4*)(fp + (size_t)(c0 + 8) * SS);
        }
        #pragma unroll
        for (int k = 0; k < 16; k++) {
            float4 a0 = *(const float4*)&sW[cur][k][te << 3];
            float4 a1 = *(const float4*)&sW[cur][k][(te << 3) + 4];
            float4 f  = *(const float4*)&sF[cur][k][ts << 2];
            float av[8] = {a0.x, a0.y, a0.z, a0.w, a1.x, a1.y, a1.z, a1.w};
            float fv[4] = {f.x, f.y, f.z, f.w};
            #pragma unroll
            for (int i = 0; i < 8; i++)
                #pragma unroll
                for (int j = 0; j < 4; j++)
                    acc[i][j] += av[i] * fv[j];
        }
        if (t < 31) {
            const int nxt = cur ^ 1;
            const int kk = wq << 2;
            sW[nxt][kk + 0][wei] = wr0.x;  sW[nxt][kk + 0][wei + 32] = wr1.x;
            sW[nxt][kk + 1][wei] = wr0.y;  sW[nxt][kk + 1][wei + 32] = wr1.y;
            sW[nxt][kk + 2][wei] = wr0.z;  sW[nxt][kk + 2][wei + 32] = wr1.z;
            sW[nxt][kk + 3][wei] = wr0.w;  sW[nxt][kk + 3][wei + 32] = wr1.w;
            *(float4*)&sF[nxt][fk][fsq]     = fr0;
            *(float4*)&sF[nxt][fk + 8][fsq] = fr1;
        }
        __syncthreads();
    }

    // epilogue: BN + ReLU, write transposed layout g_proj[b][s][e]
    float scv[8], bv[8];
    #pragma unroll
    for (int i = 0; i < 8; i++) {
        const int e = eBase + (te << 3) + i;
        scv[i] = bn_gamma[e] * rsqrtf(bn_var[e] + 1e-5f);
        bv[i]  = (conv_b[e] - bn_mean[e]) * scv[i] + bn_beta[e];
    }
    #pragma unroll
    for (int j = 0; j < 4; j++) {
        const int s = s0 + (ts << 2) + j;
        float4 o0, o1;
        o0.x = fmaxf(acc[0][j] * scv[0] + bv[0], 0.f);
        o0.y = fmaxf(acc[1][j] * scv[1] + bv[1], 0.f);
        o0.z = fmaxf(acc[2][j] * scv[2] + bv[2], 0.f);
        o0.w = fmaxf(acc[3][j] * scv[3] + bv[3], 0.f);
        o1.x = fmaxf(acc[4][j] * scv[4] + bv[4], 0.f);
        o1.y = fmaxf(acc[5][j] * scv[5] + bv[5], 0.f);
        o1.z = fmaxf(acc[6][j] * scv[6] + bv[6], 0.f);
        o1.w = fmaxf(acc[7][j] * scv[7] + bv[7], 0.f);
        float* dst = g_proj + ((size_t)b * SS + s) * EE + eBase + (te << 3);
        *(float4*)dst       = o0;
        *(float4*)(dst + 4) = o1;
    }
}

// ---------------------------------------------------------------------------
// Kernel B: pooling (coalesced via [b][s][e] layout) + 2-layer MLP (coalesced
// via transposed weights). 128 blocks x 512 threads; block owns 4 (b,n) rows.
// tid = part*128 + e; part splits s (pooling) and k (MLP) 4 ways.
// ---------------------------------------------------------------------------
__global__ void __launch_bounds__(512) kernelB(
    const float* __restrict__ b1, const float* __restrict__ b2,
    float* __restrict__ out)
{
    const int b  = blockIdx.x >> 3;
    const int ng = blockIdx.x & 7;
    const int n0 = ng * 4;
    const int tid  = threadIdx.x;
    const int e    = tid & 127;
    const int part = tid >> 7;           // 0..3

    __shared__ float mrs[4][SS];
    __shared__ float px[4][4][EE];       // partials [part][row][e]
    __shared__ float xs[4][EE];
    __shared__ float hs[4][EE];
    __shared__ float inv[4];

    for (int i = tid; i < 4 * SS; i += 512)
        mrs[i >> 8][i & 255] = g_mr[((size_t)(b * NN + n0 + (i >> 8))) * SS + (i & 255)];
    if (tid < 4) inv[tid] = g_minv[b * NN + n0 + tid];
    __syncthreads();

    // pooling: thread (e, part) covers s in [part*64, part*64+64), coalesced over e
    {
        const float* pp = g_proj + ((size_t)b * SS + part * 64) * EE + e;
        float a0 = 0.f, a1 = 0.f, a2 = 0.f, a3 = 0.f;
        #pragma unroll 8
        for (int s = 0; s < 64; s++) {
            const float p = pp[(size_t)s * EE];
            const int sg = part * 64 + s;
            a0 += p * mrs[0][sg];
            a1 += p * mrs[1][sg];
            a2 += p * mrs[2][sg];
            a3 += p * mrs[3][sg];
        }
        px[part][0][e] = a0;
        px[part][1][e] = a1;
        px[part][2][e] = a2;
        px[part][3][e] = a3;
    }
    __syncthreads();

    // reduce: thread (e, row=part)
    xs[part][e] = (px[0][part][e] + px[1][part][e] + px[2][part][e] + px[3][part][e])
                  * inv[part];
    __syncthreads();

    // layer 1 partials over k-quarter (coalesced w1T reads)
    {
        float h0 = 0.f, h1 = 0.f, h2 = 0.f, h3 = 0.f;
        const float* wt = g_w1T + (size_t)(part * 32) * EE + e;
        #pragma unroll 8
        for (int kk = 0; kk < 32; kk++) {
            const float wv = wt[(size_t)kk * EE];
            const int k = part * 32 + kk;
            h0 += wv * xs[0][k];
            h1 += wv * xs[1][k];
            h2 += wv * xs[2][k];
            h3 += wv * xs[3][k];
        }
        px[part][0][e] = h0;
        px[part][1][e] = h1;
        px[part][2][e] = h2;
        px[part][3][e] = h3;
    }
    __syncthreads();

    hs[part][e] = fmaxf(px[0][part][e] + px[1][part][e] + px[2][part][e]
                        + px[3][part][e] + b1[e], 0.f);
    __syncthreads();

    // layer 2 partials
    {
        float h0 = 0.f, h1 = 0.f, h2 = 0.f, h3 = 0.f;
        const float* wt = g_w2T + (size_t)(part * 32) * EE + e;
        #pragma unroll 8
        for (int kk = 0; kk < 32; kk++) {
            const float wv = wt[(size_t)kk * EE];
            const int k = part * 32 + kk;
            h0 += wv * hs[0][k];
            h1 += wv * hs[1][k];
            h2 += wv * hs[2][k];
            h3 += wv * hs[3][k];
        }
        px[part][0][e] = h0;
        px[part][1][e] = h1;
        px[part][2][e] = h2;
        px[part][3][e] = h3;
    }
    __syncthreads();

    out[((size_t)(b * NN + n0 + part)) * EE + e] =
        px[0][part][e] + px[1][part][e] + px[2][part][e] + px[3][part][e] + b2[e];
}

extern "C" void kernel_launch(void* const* d_in, const int* in_sizes, int n_in,
                              void* d_out, int out_size)
{
    const float* features = (const float*)d_in[0];
    const float* masks    = (const float*)d_in[1];
    const float* conv_w   = (const float*)d_in[2];
    const float* conv_b   = (const float*)d_in[3];
    const float* bn_gamma = (const float*)d_in[4];
    const float* bn_beta  = (const float*)d_in[5];
    const float* bn_mean  = (const float*)d_in[6];
    const float* bn_var   = (const float*)d_in[7];
    const float* w1       = (const float*)d_in[8];
    const float* b1       = (const float*)d_in[9];
    const float* w2       = (const float*)d_in[10];
    const float* b2       = (const float*)d_in[11];
    float* out = (float*)d_out;

    kernelA<<<642, 128>>>(features, masks, conv_w, conv_b,
                          bn_gamma, bn_beta, bn_mean, bn_var, w1, w2);
    kernelB<<<128, 512>>>(b1, b2, out);
}